// round 17
// baseline (speedup 1.0000x reference)
#include <cuda_runtime.h>
#include <cuda_fp16.h>
#include <cstdint>
#include <math.h>

// GRU-style decoder cell via mma.sync fp16 (m16n8k16, fp32 accum).
// rz fused (N=2048), 6-stage pipeline w/ 2 chunks per barrier;
// h gate 128x64 tiles at 4 CTAs/SM (4 stages, 1 chunk/barrier).
// cvt pass: block-per-segment partitioning (no per-element search).
//   r = sigmoid(x@Wr^T + hprev@Ur^T + c@Cr^T + br)   -> g_rh2 = fp16(r*hprev)
//   z = sigmoid(x@Wz^T + hprev@Uz^T + c@Cz^T + bz)   -> g_z (fp32)
//   h = tanh   (x@Wh^T + g_rh2@Uh^T + c@Ch^T + bh)   -> out = z*h + (1-z)*hprev

#define BATCH 8192
#define HID   1024
#define BM 128
#define BK 32            // halves per chunk
#define NCHUNK 128       // 4096 / 32

#define A_TILE (BM * BK) // 4096 halves

// ---- scratch (allocation-free) ----
__device__ __half g_x2 [(size_t)BATCH * 1024];
__device__ __half g_h2 [(size_t)BATCH * 1024];
__device__ __half g_c2 [(size_t)BATCH * 2048];
__device__ __half g_rh2[(size_t)BATCH * HID];
__device__ float  g_z  [(size_t)BATCH * HID];
__device__ __half g_w2 [(size_t)12 * 1024 * 1024];

__device__ __forceinline__ void cp16(void* dst_smem, const void* src) {
    uint32_t d = (uint32_t)__cvta_generic_to_shared(dst_smem);
    asm volatile("cp.async.cg.shared.global [%0], [%1], 16;" :: "r"(d), "l"(src));
}
__device__ __forceinline__ void cp_commit() {
    asm volatile("cp.async.commit_group;" ::: "memory");
}
__device__ __forceinline__ void cp_wait2() {
    asm volatile("cp.async.wait_group 2;" ::: "memory");
}
__device__ __forceinline__ uint32_t h2_bits(__half2 h) {
    return *reinterpret_cast<uint32_t*>(&h);
}
__device__ __forceinline__ void mma_f16(float* c, uint32_t a0, uint32_t a1,
                                        uint32_t a2, uint32_t a3,
                                        uint32_t b0, uint32_t b1) {
    asm volatile(
        "mma.sync.aligned.m16n8k16.row.col.f32.f16.f16.f32 "
        "{%0,%1,%2,%3}, {%4,%5,%6,%7}, {%8,%9}, {%0,%1,%2,%3};"
        : "+f"(c[0]), "+f"(c[1]), "+f"(c[2]), "+f"(c[3])
        : "r"(a0), "r"(a1), "r"(a2), "r"(a3), "r"(b0), "r"(b1));
}
__device__ __forceinline__ float fsigmoid(float v) { return 1.0f / (1.0f + __expf(-v)); }
__device__ __forceinline__ float ftanh(float v) {
    float e = __expf(-2.0f * v);
    return 2.0f / (1.0f + e) - 1.0f;
}

// ---- fp32 -> fp16 conversion: block-per-segment partitioning ----
#define NSEG 12
struct CvtSegs {
    const float4* src[NSEG];
    uint2*        dst[NSEG];
    int           n4[NSEG];        // float4 count per segment
    int           blk_off[NSEG + 1];  // prefix of blocks assigned per segment
};

__global__ __launch_bounds__(256)
void cvt_all_kernel(const __grid_constant__ CvtSegs segs)
{
    // resolve segment once per block (scalar, 12 iterations)
    int s = 0;
#pragma unroll
    for (int k = 1; k < NSEG; ++k)
        if ((int)blockIdx.x >= segs.blk_off[k]) s = k;

    const float4* __restrict__ src = segs.src[s];
    uint2*        __restrict__ dst = segs.dst[s];
    const int n4     = segs.n4[s];
    const int nblk   = segs.blk_off[s + 1] - segs.blk_off[s];
    const int bidx   = (int)blockIdx.x - segs.blk_off[s];
    const int stride = nblk * 256;

    for (int j = bidx * 256 + threadIdx.x; j < n4; j += stride) {
        const float4 v = src[j];
        uint2 o;
        o.x = h2_bits(__floats2half2_rn(v.x, v.y));
        o.y = h2_bits(__floats2half2_rn(v.z, v.w));
        dst[j] = o;
    }
}

// mode 0: fused rz (bn<1024 -> rh2 fp16; else -> z fp32)
// mode 2: final h   (out = z*tanh + (1-z)*hprev)
// Pipeline invariant: prefill = NSTAGES - BATCH_CH groups; cp_wait2 leaves <=2
// groups pending, so (prefill - 2) == BATCH_CH chunks are guaranteed complete.
template <int BN_, int THREADS, int MAXCTA, int NSTAGES, int BATCH_CH>
__global__ __launch_bounds__(THREADS, MAXCTA)
void gate_mma_kernel(
    const __half* __restrict__ x,
    const __half* __restrict__ A1,
    const __half* __restrict__ c,
    const __half* __restrict__ W0,
    const __half* __restrict__ W1,
    const __half* __restrict__ W2,
    const float* __restrict__ bias_a,
    const float* __restrict__ bias_b,
    const float* __restrict__ hprev,
    const float* __restrict__ zbuf,
    __half* __restrict__ out_h,
    float* __restrict__ out_f,
    int mode)
{
    constexpr int B_TILE = BN_ * BK;
    constexpr int BNW = BN_ / 32;
    constexpr int PREFILL = NSTAGES - BATCH_CH;
    static_assert(PREFILL - 2 == BATCH_CH, "wait_group 2 must guarantee BATCH_CH chunks");

    extern __shared__ __half sh[];
    __half* As = sh;
    __half* Bs = sh + NSTAGES * A_TILE;

    const int tid  = threadIdx.x;
    const int lane = tid & 31;
    const int wid  = tid >> 5;
    const int g    = lane >> 2;
    const int tg   = lane & 3;
    const int wm   = wid / BNW;
    const int wn   = wid % BNW;

    const int bm = blockIdx.y * BM;
    const int bn = blockIdx.x * BN_;

    const int loff = ((tg ^ (g & 3)) << 3);

    float acc[4][4][4];
#pragma unroll
    for (int i = 0; i < 4; ++i)
#pragma unroll
        for (int j = 0; j < 4; ++j)
#pragma unroll
            for (int k = 0; k < 4; ++k)
                acc[i][j][k] = 0.0f;

    auto issue = [&](int i) {
        const int s = i % NSTAGES;
        const __half* Aseg;
        const __half* Wseg;
        int ld, k0;
        if (i < 32)      { Aseg = x;  Wseg = W0; ld = 1024; k0 = i * BK; }
        else if (i < 64) { Aseg = A1; Wseg = W1; ld = 1024; k0 = (i - 32) * BK; }
        else             { Aseg = c;  Wseg = W2; ld = 2048; k0 = (i - 64) * BK; }

        __half* ad = As + s * A_TILE;
        __half* bd = Bs + s * B_TILE;
#pragma unroll
        for (int j = 0; j < 512 / THREADS; ++j) {
            const int idx = tid + j * THREADS;
            const int row = idx >> 2;
            const int ch  = idx & 3;
            const int swc = ch ^ (row & 3);
            cp16(ad + row * 32 + (swc << 3),
                 Aseg + (size_t)(bm + row) * ld + k0 + (ch << 3));
        }
#pragma unroll
        for (int j = 0; j < (BN_ * 4) / THREADS; ++j) {
            const int idx = tid + j * THREADS;
            const int row = idx >> 2;
            const int ch  = idx & 3;
            const int swc = ch ^ (row & 3);
            cp16(bd + row * 32 + (swc << 3),
                 Wseg + (size_t)(bn + row) * ld + k0 + (ch << 3));
        }
        cp_commit();
    };

    auto consume = [&](int i) {
        const int buf = i % NSTAGES;
        const __half* A0 = As + buf * A_TILE + (wm * 64) * 32;
        const __half* B0 = Bs + buf * B_TILE + (wn * 32) * 32;

        uint4 bv[4];
#pragma unroll
        for (int nf = 0; nf < 4; ++nf)
            bv[nf] = *(const uint4*)(B0 + (nf * 8 + g) * 32 + loff);

#pragma unroll
        for (int mf = 0; mf < 4; ++mf) {
            const uint4 a0 = *(const uint4*)(A0 + (mf * 16 + g) * 32 + loff);
            const uint4 a1 = *(const uint4*)(A0 + (mf * 16 + g + 8) * 32 + loff);
#pragma unroll
            for (int nf = 0; nf < 4; ++nf)
                mma_f16(acc[mf][nf], a0.x, a1.x, a0.y, a1.y, bv[nf].x, bv[nf].y);
#pragma unroll
            for (int nf = 0; nf < 4; ++nf)
                mma_f16(acc[mf][nf], a0.z, a1.z, a0.w, a1.w, bv[nf].z, bv[nf].w);
        }
    };

    // prefill
#pragma unroll
    for (int p = 0; p < PREFILL; ++p) issue(p);

    for (int i = 0; i < NCHUNK; i += BATCH_CH) {
        cp_wait2();           // guarantees chunks i..i+BATCH_CH-1 complete
        __syncthreads();
        // issue into slots consumed during the PREVIOUS iteration
#pragma unroll
        for (int b = 0; b < BATCH_CH; ++b) {
            const int nx = i + PREFILL + b;
            if (nx < NCHUNK) issue(nx);
        }
#pragma unroll
        for (int b = 0; b < BATCH_CH; ++b)
            consume(i + b);
    }

    // ---- epilogue ----
    const bool is_r = (bn < 1024);
    const float* bias = (mode == 2) ? bias_a : (is_r ? bias_a : bias_b - 1024);

#pragma unroll
    for (int mf = 0; mf < 4; ++mf) {
#pragma unroll
        for (int nf = 0; nf < 4; ++nf) {
            const int n = bn + wn * 32 + nf * 8 + 2 * tg;
            const float2 bi = *(const float2*)(bias + n);
#pragma unroll
            for (int half = 0; half < 2; ++half) {
                const int m = bm + wm * 64 + mf * 16 + g + half * 8;
                float v0 = acc[mf][nf][2 * half + 0] + bi.x;
                float v1 = acc[mf][nf][2 * half + 1] + bi.y;
                if (mode == 0) {
                    if (is_r) {
                        const size_t idx = (size_t)m * HID + n;
                        const float2 hp = *(const float2*)(hprev + idx);
                        *(__half2*)(out_h + idx) =
                            __floats2half2_rn(fsigmoid(v0) * hp.x, fsigmoid(v1) * hp.y);
                    } else {
                        const size_t idx = (size_t)m * HID + (n - 1024);
                        float2 o;
                        o.x = fsigmoid(v0);
                        o.y = fsigmoid(v1);
                        *(float2*)(out_f + idx) = o;
                    }
                } else {
                    const size_t idx = (size_t)m * HID + n;
                    const float2 hp = *(const float2*)(hprev + idx);
                    const float2 zz = *(const float2*)(zbuf + idx);
                    float2 o;
                    o.x = fmaf(zz.x, ftanh(v0) - hp.x, hp.x);
                    o.y = fmaf(zz.y, ftanh(v1) - hp.y, hp.y);
                    *(float2*)(out_f + idx) = o;
                }
            }
        }
    }
}

extern "C" void kernel_launch(void* const* d_in, const int* in_sizes, int n_in,
                              void* d_out, int out_size)
{
    const float* x     = (const float*)d_in[0];
    const float* hprev = (const float*)d_in[1];
    const float* c     = (const float*)d_in[2];
    const float* Wh    = (const float*)d_in[3];
    const float* Wz    = (const float*)d_in[4];
    const float* Wr    = (const float*)d_in[5];
    const float* Uh    = (const float*)d_in[6];
    const float* Uz    = (const float*)d_in[7];
    const float* Ur    = (const float*)d_in[8];
    const float* Ch    = (const float*)d_in[9];
    const float* Cz    = (const float*)d_in[10];
    const float* Cr    = (const float*)d_in[11];
    const float* bh    = (const float*)d_in[12];
    const float* bz    = (const float*)d_in[13];
    const float* br    = (const float*)d_in[14];
    float* out = (float*)d_out;

    __half *x2, *h2, *c2, *rh2, *w2;
    float *z_p;
    cudaGetSymbolAddress((void**)&x2,  g_x2);
    cudaGetSymbolAddress((void**)&h2,  g_h2);
    cudaGetSymbolAddress((void**)&c2,  g_c2);
    cudaGetSymbolAddress((void**)&rh2, g_rh2);
    cudaGetSymbolAddress((void**)&z_p, g_z);
    cudaGetSymbolAddress((void**)&w2,  g_w2);

    const size_t M1 = (size_t)1024 * 1024;
    __half* rzW = w2;                 // [2048,1024]
    __half* rzU = w2 + 2 * M1;        // [2048,1024]
    __half* rzC = w2 + 4 * M1;        // [2048,2048]
    __half* hW  = w2 + 8 * M1;        // [1024,1024]
    __half* hU  = w2 + 9 * M1;
    __half* hC  = w2 + 10 * M1;       // [1024,2048]

    // ---- one conversion launch, 12 segments, blocks partitioned by size ----
    CvtSegs segs;
    const float* srcs[NSEG] = { x, hprev, c,
                                Wr, Wz, Ur, Uz, Cr, Cz,
                                Wh, Uh, Ch };
    __half* dsts[NSEG] = { x2, h2, c2,
                           rzW, rzW + M1, rzU, rzU + M1, rzC, rzC + 2 * M1,
                           hW, hU, hC };
    const size_t cnts[NSEG] = { (size_t)BATCH * 1024, (size_t)BATCH * 1024, (size_t)BATCH * 2048,
                                M1, M1, M1, M1, 2 * M1, 2 * M1,
                                M1, M1, 2 * M1 };
    const int TOTAL_BLOCKS = 2960;
    size_t total_elems = 0;
    for (int s = 0; s < NSEG; ++s) total_elems += cnts[s];
    int used = 0;
    for (int s = 0; s < NSEG; ++s) {
        segs.src[s] = (const float4*)srcs[s];
        segs.dst[s] = (uint2*)dsts[s];
        segs.n4[s]  = (int)(cnts[s] / 4);
        segs.blk_off[s] = used;
        int nb = (int)(((double)cnts[s] / (double)total_elems) * TOTAL_BLOCKS);
        if (nb < 1) nb = 1;
        used += nb;
    }
    segs.blk_off[NSEG] = used;
    cvt_all_kernel<<<used, 256>>>(segs);

    // rz: BN=128, 256 thr, 2 CTAs/SM, 6 stages, 2 chunks/barrier (prefill 4)
    constexpr int SMEM_RZ = 6 * (A_TILE + 128 * BK) * 2;   // 98304
    // h: BN=64, 128 thr, 4 CTAs/SM, 4 stages, 1 chunk/barrier (prefill 3)
    constexpr int SMEM_H  = 4 * (A_TILE + 64 * BK) * 2;    // 49152

    cudaFuncSetAttribute((const void*)gate_mma_kernel<128, 256, 2, 6, 2>,
                         cudaFuncAttributeMaxDynamicSharedMemorySize, SMEM_RZ);
    cudaFuncSetAttribute((const void*)gate_mma_kernel<64, 128, 4, 4, 1>,
                         cudaFuncAttributeMaxDynamicSharedMemorySize, SMEM_H);

    // fused r+z: N = 2048, grid (16, 64) = 1024 CTAs
    gate_mma_kernel<128, 256, 2, 6, 2><<<dim3(2048 / 128, BATCH / BM), 256, SMEM_RZ>>>(
        x2, h2, c2, rzW, rzU, rzC, br, bz, hprev, nullptr, rh2, z_p, 0);
    // h gate: N = 1024, BN=64 -> grid (16, 64) = 1024 CTAs, 4/SM
    gate_mma_kernel<64, 128, 4, 4, 1><<<dim3(1024 / 64, BATCH / BM), 128, SMEM_H>>>(
        x2, rh2, c2, hW, hU, hC, bh, nullptr, hprev, z_p, nullptr, out, 2);
}